// round 1
// baseline (speedup 1.0000x reference)
#include <cuda_runtime.h>
#include <cuda_bf16.h>
#include <math.h>

// Problem constants: B=2, H=16, L=2048, D=128, BLKQ=BLKK=64, topk=4
#define B_    2
#define H_    16
#define L_    2048
#define D_    128
#define BH    32          // B*H
#define NBLK  32          // L/64
#define TOPK  4
#define KVSTRIDE 132      // padded smem row stride (floats) for conflict-free LDS.128

// ---------------- static device scratch (no allocations allowed) ----------------
__device__ float g_qb[BH*NBLK*D_];      // block means of q
__device__ float g_kb[BH*NBLK*D_];      // block means of k
__device__ int   g_lut[BH*NBLK*TOPK];   // top-4 k-block indices per q-block
__device__ float g_kvsum[BH*D_*D_];     // sum_l phi_k[l,d] * v[l,e]
__device__ float g_ksum [BH*D_];        // sum_l phi_k[l,d]
__device__ float g_M    [BH*D_*D_];     // kvsum @ w_proj^T

// ---------------- kernel 1: block means of q and k ----------------
__global__ void k_blockmean(const float* __restrict__ q, const float* __restrict__ k)
{
    int id    = blockIdx.x;          // 0..2047 : [which][bh*32+blk]
    int which = id >> 10;
    int rem   = id & 1023;
    const float* src = which ? k : q;
    float*       dst = which ? g_kb : g_qb;
    int d = threadIdx.x;             // 0..127
    const float* base = src + (size_t)rem * 64 * D_ + d;
    float s = 0.f;
#pragma unroll 8
    for (int r = 0; r < 64; r++) s += base[r * D_];
    dst[rem * D_ + d] = s * (1.0f / 64.0f);
}

// ---------------- kernel 2: block scores + top-4 selection ----------------
__global__ void k_topk()
{
    int id   = blockIdx.x;           // bh*32 + qblk, 0..1023
    int bh   = id >> 5;
    int lane = threadIdx.x;          // 32 threads: lane = k-block index
    const float4* q4 = (const float4*)(g_qb + id * D_);
    const float4* k4 = (const float4*)(g_kb + (bh * NBLK + lane) * D_);
    float s = 0.f;
#pragma unroll
    for (int d4 = 0; d4 < 32; d4++) {
        float4 a = q4[d4], b = k4[d4];
        s += a.x*b.x + a.y*b.y + a.z*b.z + a.w*b.w;
    }
    float val = s;
    for (int t = 0; t < TOPK; t++) {
        float m = val; int mi = lane;
#pragma unroll
        for (int o = 16; o > 0; o >>= 1) {
            float ov = __shfl_xor_sync(0xffffffffu, m,  o);
            int   oi = __shfl_xor_sync(0xffffffffu, mi, o);
            if (ov > m || (ov == m && oi < mi)) { m = ov; mi = oi; }
        }
        if (lane == 0)  g_lut[id * TOPK + t] = mi;
        if (lane == mi) val = -3.0e38f;
    }
}

// ---------------- kernel 3: sparse block attention ----------------
// One block per (bh, qblock). smem: Q 64x128 | KV 128x132 (2 k-blocks) | S 64x256
__global__ void __launch_bounds__(256, 1)
k_sparse(const float* __restrict__ q, const float* __restrict__ k,
         const float* __restrict__ v, float* __restrict__ out)
{
    extern __shared__ float sm[];
    float* Qs = sm;                       // 64*128   = 8192 floats
    float* KV = Qs + 64 * D_;             // 128*132  = 16896 floats
    float* S  = KV + 128 * KVSTRIDE;      // 64*256   = 16384 floats

    int id = blockIdx.x;                  // bh*32 + qb
    int bh = id >> 5, qb = id & 31;
    int tid  = threadIdx.x;
    int warp = tid >> 5, lane = tid & 31;
    const size_t bh_off = (size_t)bh * L_ * D_;

    // load Q tile
    const float4* qg4 = (const float4*)(q + bh_off + (size_t)qb * 64 * D_);
    float4* Qs4 = (float4*)Qs;
    for (int i = tid; i < 64 * 32; i += 256) Qs4[i] = qg4[i];

    int blks[4];
#pragma unroll
    for (int t = 0; t < 4; t++) blks[t] = g_lut[id * TOPK + t];
    const float scale = 0.088388347648318447f;   // 1/sqrt(128)

    // ---- S = Q @ K^T * scale, two passes of 2 k-blocks each ----
    for (int pass = 0; pass < 2; pass++) {
        __syncthreads();
        for (int idx = tid; idx < 128 * 32; idx += 256) {
            int row = idx >> 5, c4 = idx & 31;
            int blk = blks[pass * 2 + (row >> 6)];
            int gr  = blk * 64 + (row & 63);
            float4 val = ((const float4*)(k + bh_off + (size_t)gr * D_))[c4];
            *(float4*)&KV[row * KVSTRIDE + c4 * 4] = val;
        }
        __syncthreads();
        // 8 i's per warp-group, 4 interleaved j's per lane: 8x4 register tile
        float acc[8][4];
#pragma unroll
        for (int a = 0; a < 8; a++)
#pragma unroll
            for (int b2 = 0; b2 < 4; b2++) acc[a][b2] = 0.f;
        for (int d4 = 0; d4 < 32; d4++) {
            float4 kr[4];
#pragma unroll
            for (int jj = 0; jj < 4; jj++)
                kr[jj] = *(const float4*)&KV[(lane + jj * 32) * KVSTRIDE + d4 * 4];
#pragma unroll
            for (int ii = 0; ii < 8; ii++) {
                float4 qv = Qs4[(warp * 8 + ii) * 32 + d4];
#pragma unroll
                for (int jj = 0; jj < 4; jj++)
                    acc[ii][jj] += qv.x*kr[jj].x + qv.y*kr[jj].y + qv.z*kr[jj].z + qv.w*kr[jj].w;
            }
        }
#pragma unroll
        for (int ii = 0; ii < 8; ii++)
#pragma unroll
            for (int jj = 0; jj < 4; jj++)
                S[(warp * 8 + ii) * 256 + pass * 128 + lane + jj * 32] = acc[ii][jj] * scale;
    }
    __syncthreads();

    // ---- row softmax over 256 ----
    for (int i = warp; i < 64; i += 8) {
        float vals[8]; float mx = -3.0e38f;
#pragma unroll
        for (int c = 0; c < 8; c++) { vals[c] = S[i * 256 + lane + c * 32]; mx = fmaxf(mx, vals[c]); }
#pragma unroll
        for (int o = 16; o > 0; o >>= 1) mx = fmaxf(mx, __shfl_xor_sync(0xffffffffu, mx, o));
        float sum = 0.f;
#pragma unroll
        for (int c = 0; c < 8; c++) { vals[c] = __expf(vals[c] - mx); sum += vals[c]; }
#pragma unroll
        for (int o = 16; o > 0; o >>= 1) sum += __shfl_xor_sync(0xffffffffu, sum, o);
        float inv = 1.f / sum;
#pragma unroll
        for (int c = 0; c < 8; c++) S[i * 256 + lane + c * 32] = vals[c] * inv;
    }

    // ---- O = P @ V, two passes ----
    float4 o4[8];
#pragma unroll
    for (int ii = 0; ii < 8; ii++) o4[ii] = make_float4(0.f, 0.f, 0.f, 0.f);
    for (int pass = 0; pass < 2; pass++) {
        __syncthreads();
        for (int idx = tid; idx < 128 * 32; idx += 256) {
            int row = idx >> 5, c4 = idx & 31;
            int blk = blks[pass * 2 + (row >> 6)];
            int gr  = blk * 64 + (row & 63);
            float4 val = ((const float4*)(v + bh_off + (size_t)gr * D_))[c4];
            *(float4*)&KV[row * KVSTRIDE + c4 * 4] = val;
        }
        __syncthreads();
        for (int j = 0; j < 128; j++) {
            float4 v4 = *(const float4*)&KV[j * KVSTRIDE + lane * 4];
#pragma unroll
            for (int ii = 0; ii < 8; ii++) {
                float p = S[(warp * 8 + ii) * 256 + pass * 128 + j];
                o4[ii].x += p * v4.x; o4[ii].y += p * v4.y;
                o4[ii].z += p * v4.z; o4[ii].w += p * v4.w;
            }
        }
    }
    float4* out4 = (float4*)(out + bh_off + (size_t)qb * 64 * D_);
#pragma unroll
    for (int ii = 0; ii < 8; ii++)
        out4[(warp * 8 + ii) * 32 + lane] = o4[ii];
}

// ---------------- kernel 4: kvsum / ksum (phi_k computed on the fly) ----------------
// grid = BH * 8 chunks of 256 tokens; 8x8 register tile per thread; atomic reduce.
__global__ void __launch_bounds__(256)
k_kv(const float* __restrict__ k, const float* __restrict__ v)
{
    __shared__ float ph[8][128];
    __shared__ float vv[8][128];
    int bh    = blockIdx.x >> 3;
    int chunk = blockIdx.x & 7;
    int tid  = threadIdx.x;
    int warp = tid >> 5, lane = tid & 31;
    int dg   = tid >> 4, eg = tid & 15;

    float acc[8][8];
#pragma unroll
    for (int a = 0; a < 8; a++)
#pragma unroll
        for (int b2 = 0; b2 < 8; b2++) acc[a][b2] = 0.f;
    float ks_acc[8];
#pragma unroll
    for (int a = 0; a < 8; a++) ks_acc[a] = 0.f;

    const size_t bh_off = (size_t)bh * L_ * D_;
    for (int it = 0; it < 32; it++) {
        int l0 = chunk * 256 + it * 8;
        {   // warp w loads & softmaxes row l0+w, stages v row
            size_t l = bh_off + (size_t)(l0 + warp) * D_;
            float4 a = ((const float4*)(k + l))[lane];
            float m = fmaxf(fmaxf(a.x, a.y), fmaxf(a.z, a.w));
#pragma unroll
            for (int o = 16; o > 0; o >>= 1) m = fmaxf(m, __shfl_xor_sync(0xffffffffu, m, o));
            float ex = __expf(a.x - m), ey = __expf(a.y - m);
            float ez = __expf(a.z - m), ew = __expf(a.w - m);
            float s = ex + ey + ez + ew;
#pragma unroll
            for (int o = 16; o > 0; o >>= 1) s += __shfl_xor_sync(0xffffffffu, s, o);
            float inv = 1.f / s;
            *(float4*)&ph[warp][lane * 4] = make_float4(ex*inv, ey*inv, ez*inv, ew*inv);
            *(float4*)&vv[warp][lane * 4] = ((const float4*)(v + l))[lane];
        }
        __syncthreads();
#pragma unroll
        for (int r = 0; r < 8; r++) {
            float4 pA = *(const float4*)&ph[r][dg * 8];
            float4 pB = *(const float4*)&ph[r][dg * 8 + 4];
            float4 vA = *(const float4*)&vv[r][eg * 8];
            float4 vB = *(const float4*)&vv[r][eg * 8 + 4];
            float pd[8] = {pA.x,pA.y,pA.z,pA.w,pB.x,pB.y,pB.z,pB.w};
            float ve[8] = {vA.x,vA.y,vA.z,vA.w,vB.x,vB.y,vB.z,vB.w};
#pragma unroll
            for (int a = 0; a < 8; a++) {
#pragma unroll
                for (int b2 = 0; b2 < 8; b2++) acc[a][b2] += pd[a] * ve[b2];
                if (eg == 0) ks_acc[a] += pd[a];
            }
        }
        __syncthreads();
    }
    float* kvp = g_kvsum + bh * D_ * D_;
#pragma unroll
    for (int a = 0; a < 8; a++)
#pragma unroll
        for (int b2 = 0; b2 < 8; b2++)
            atomicAdd(&kvp[(dg * 8 + a) * D_ + eg * 8 + b2], acc[a][b2]);
    if (eg == 0) {
#pragma unroll
        for (int a = 0; a < 8; a++)
            atomicAdd(&g_ksum[bh * D_ + dg * 8 + a], ks_acc[a]);
    }
}

// ---------------- kernel 5: M = kvsum @ w_proj^T (per bh) ----------------
__global__ void __launch_bounds__(256)
k_M(const float* __restrict__ w)
{
    extern __shared__ float sm[];
    float* kvt = sm;                      // [e][d], stride 132
    float* wt  = sm + 128 * KVSTRIDE;     // [e][d'], stride 132
    int bh = blockIdx.x;
    int tid = threadIdx.x;
    const float* kv = g_kvsum + bh * D_ * D_;
    for (int idx = tid; idx < D_ * D_; idx += 256) {
        int d = idx >> 7, e = idx & 127;
        kvt[e * KVSTRIDE + d] = kv[idx];       // kv[d][e] -> kvt[e][d]
        wt [e * KVSTRIDE + d] = w[idx];        // w[d'][e] -> wt[e][d']
    }
    __syncthreads();
    int dg = tid >> 4, eg = tid & 15;
    float acc[8][8];
#pragma unroll
    for (int a = 0; a < 8; a++)
#pragma unroll
        for (int b2 = 0; b2 < 8; b2++) acc[a][b2] = 0.f;
    for (int e = 0; e < 128; e++) {
        float4 aA = *(const float4*)&kvt[e * KVSTRIDE + dg * 8];
        float4 aB = *(const float4*)&kvt[e * KVSTRIDE + dg * 8 + 4];
        float4 bA = *(const float4*)&wt [e * KVSTRIDE + eg * 8];
        float4 bB = *(const float4*)&wt [e * KVSTRIDE + eg * 8 + 4];
        float ad[8] = {aA.x,aA.y,aA.z,aA.w,aB.x,aB.y,aB.z,aB.w};
        float bd[8] = {bA.x,bA.y,bA.z,bA.w,bB.x,bB.y,bB.z,bB.w};
#pragma unroll
        for (int a = 0; a < 8; a++)
#pragma unroll
            for (int b2 = 0; b2 < 8; b2++) acc[a][b2] += ad[a] * bd[b2];
    }
    float* Mp = g_M + bh * D_ * D_;
#pragma unroll
    for (int a = 0; a < 8; a++)
#pragma unroll
        for (int b2 = 0; b2 < 8; b2++)
            Mp[(dg * 8 + a) * D_ + eg * 8 + b2] = acc[a][b2];
}

// ---------------- kernel 6: out += (phi_q @ M)/den + b ----------------
// One block per (bh, 64-token chunk). phi_q computed on the fly.
__global__ void __launch_bounds__(256)
k_lin_out(const float* __restrict__ q, const float* __restrict__ bias,
          float* __restrict__ out)
{
    extern __shared__ float sm[];
    float* Ms    = sm;                // 16384
    float* phis  = Ms + D_ * D_;      // 64*128
    float* ksums = phis + 64 * D_;    // 128
    float* dens  = ksums + D_;        // 64
    int bh = blockIdx.x >> 5, cb = blockIdx.x & 31;
    int tid = threadIdx.x, warp = tid >> 5, lane = tid & 31;

    for (int idx = tid; idx < D_ * D_; idx += 256) Ms[idx] = g_M[bh * D_ * D_ + idx];
    if (tid < D_) ksums[tid] = g_ksum[bh * D_ + tid];
    __syncthreads();

    const size_t base = (size_t)bh * L_ * D_ + (size_t)cb * 64 * D_;
    for (int rr = 0; rr < 8; rr++) {
        int row = warp + rr * 8;
        float4 a = ((const float4*)(q + base + (size_t)row * D_))[lane];
        float m = fmaxf(fmaxf(a.x, a.y), fmaxf(a.z, a.w));
#pragma unroll
        for (int o = 16; o > 0; o >>= 1) m = fmaxf(m, __shfl_xor_sync(0xffffffffu, m, o));
        float ex = __expf(a.x - m), ey = __expf(a.y - m);
        float ez = __expf(a.z - m), ew = __expf(a.w - m);
        float s = ex + ey + ez + ew;
#pragma unroll
        for (int o = 16; o > 0; o >>= 1) s += __shfl_xor_sync(0xffffffffu, s, o);
        float inv = 1.f / s;
        float4 p = make_float4(ex*inv, ey*inv, ez*inv, ew*inv);
        *(float4*)&phis[row * D_ + lane * 4] = p;
        float4 ksv = ((const float4*)ksums)[lane];
        float dp = p.x*ksv.x + p.y*ksv.y + p.z*ksv.z + p.w*ksv.w;
#pragma unroll
        for (int o = 16; o > 0; o >>= 1) dp += __shfl_xor_sync(0xffffffffu, dp, o);
        if (lane == 0) dens[row] = 1e-5f + dp;
    }
    __syncthreads();

    // out[t][d'] = sum_d phi[t][d] * M[d][d']   (8 tokens per warp, float4 d' per lane)
    float4 acc[8];
#pragma unroll
    for (int tt = 0; tt < 8; tt++) acc[tt] = make_float4(0.f, 0.f, 0.f, 0.f);
    const float4* Ms4 = (const float4*)Ms;
    for (int d = 0; d < 128; d++) {
        float4 m4 = Ms4[d * 32 + lane];
#pragma unroll
        for (int tt = 0; tt < 8; tt++) {
            float p = phis[(warp * 8 + tt) * D_ + d];
            acc[tt].x += p * m4.x; acc[tt].y += p * m4.y;
            acc[tt].z += p * m4.z; acc[tt].w += p * m4.w;
        }
    }
    float4 b4 = ((const float4*)bias)[lane];
    float4* out4 = (float4*)(out + base);
#pragma unroll
    for (int tt = 0; tt < 8; tt++) {
        int t = warp * 8 + tt;
        float inv = 1.f / dens[t];
        float4 pr = out4[t * 32 + lane];
        pr.x += acc[tt].x * inv + b4.x;
        pr.y += acc[tt].y * inv + b4.y;
        pr.z += acc[tt].z * inv + b4.z;
        pr.w += acc[tt].w * inv + b4.w;
        out4[t * 32 + lane] = pr;
    }
}

// ---------------- launch ----------------
extern "C" void kernel_launch(void* const* d_in, const int* in_sizes, int n_in,
                              void* d_out, int out_size)
{
    const float* q  = (const float*)d_in[0];
    const float* k  = (const float*)d_in[1];
    const float* v  = (const float*)d_in[2];
    const float* w  = (const float*)d_in[3];
    const float* bp = (const float*)d_in[4];
    float* out = (float*)d_out;

    const int sp_smem = (64*D_ + 128*KVSTRIDE + 64*256) * (int)sizeof(float);   // 165888
    const int m_smem  = (2 * 128 * KVSTRIDE) * (int)sizeof(float);              // 135168
    const int lo_smem = (D_*D_ + 64*D_ + D_ + 64) * (int)sizeof(float);         //  99072

    cudaFuncSetAttribute(k_sparse,  cudaFuncAttributeMaxDynamicSharedMemorySize, sp_smem);
    cudaFuncSetAttribute(k_M,       cudaFuncAttributeMaxDynamicSharedMemorySize, m_smem);
    cudaFuncSetAttribute(k_lin_out, cudaFuncAttributeMaxDynamicSharedMemorySize, lo_smem);

    void* kvp = nullptr; void* ksp = nullptr;
    cudaGetSymbolAddress(&kvp, g_kvsum);
    cudaGetSymbolAddress(&ksp, g_ksum);
    cudaMemsetAsync(kvp, 0, sizeof(float) * BH * D_ * D_);
    cudaMemsetAsync(ksp, 0, sizeof(float) * BH * D_);

    k_blockmean<<<2048, 128>>>(q, k);
    k_topk<<<1024, 32>>>();
    k_sparse<<<1024, 256, sp_smem>>>(q, k, v, out);
    k_kv<<<256, 256>>>(k, v);
    k_M<<<32, 256, m_smem>>>(w);
    k_lin_out<<<1024, 256, lo_smem>>>(q, bp, out);
}

// round 3
// speedup vs baseline: 1.1194x; 1.1194x over previous
#include <cuda_runtime.h>
#include <cuda_bf16.h>
#include <math.h>
#include <stdint.h>

// Problem constants: B=2, H=16, L=2048, D=128, BLKQ=BLKK=64, topk=4
#define B_    2
#define H_    16
#define L_    2048
#define D_    128
#define BH    32
#define NBLK  32
#define TOPK  4

#define QSTR 132     // stride for Q/K/phi tiles
#define VSTR 136     // stride for V/M tiles
#define SSTR 260     // stride for S tile
#define PSTR 136

// ---------------- static device scratch ----------------
__device__ float g_qb[BH*NBLK*D_];
__device__ float g_kb[BH*NBLK*D_];
__device__ int   g_lut[BH*NBLK*TOPK];
__device__ float g_kvsum[BH*D_*D_];
__device__ float g_ksum [BH*D_];
__device__ float g_M    [BH*D_*D_];

// ---------------- tf32 mma helpers ----------------
__device__ __forceinline__ void mma8(float c[4],
                                     uint32_t a0, uint32_t a1, uint32_t a2, uint32_t a3,
                                     uint32_t b0, uint32_t b1)
{
    asm volatile(
        "mma.sync.aligned.m16n8k8.row.col.f32.tf32.tf32.f32 "
        "{%0,%1,%2,%3},{%4,%5,%6,%7},{%8,%9},{%0,%1,%2,%3};\n"
        : "+f"(c[0]), "+f"(c[1]), "+f"(c[2]), "+f"(c[3])
        : "r"(a0), "r"(a1), "r"(a2), "r"(a3), "r"(b0), "r"(b1));
}

__device__ __forceinline__ uint32_t tf32_rna(float x)
{
    uint32_t r;
    asm("cvt.rna.tf32.f32 %0, %1;" : "=r"(r) : "f"(x));
    return r;
}

__device__ __forceinline__ void split_tf32(float x, uint32_t& h, uint32_t& l)
{
    h = tf32_rna(x);
    l = tf32_rna(x - __uint_as_float(h));
}

// 3xTF32: c += a*b with fp32-like accuracy (a,b given as fp32 fragments)
__device__ __forceinline__ void mma3(float c[4],
                                     const uint32_t ah[4], const uint32_t al[4],
                                     const uint32_t bh[2], const uint32_t bl[2])
{
    mma8(c, ah[0], ah[1], ah[2], ah[3], bh[0], bh[1]);
    mma8(c, ah[0], ah[1], ah[2], ah[3], bl[0], bl[1]);
    mma8(c, al[0], al[1], al[2], al[3], bh[0], bh[1]);
}

// ---------------- kernel 1: block means ----------------
__global__ void k_blockmean(const float* __restrict__ q, const float* __restrict__ k)
{
    int id    = blockIdx.x;
    int which = id >> 10;
    int rem   = id & 1023;
    const float* src = which ? k : q;
    float*       dst = which ? g_kb : g_qb;
    int d = threadIdx.x;
    const float* base = src + (size_t)rem * 64 * D_ + d;
    float s = 0.f;
#pragma unroll 8
    for (int r = 0; r < 64; r++) s += base[r * D_];
    dst[rem * D_ + d] = s * (1.0f / 64.0f);
}

// ---------------- kernel 2: top-4 selection ----------------
__global__ void k_topk()
{
    int id   = blockIdx.x;
    int bh   = id >> 5;
    int lane = threadIdx.x;
    const float4* q4 = (const float4*)(g_qb + id * D_);
    const float4* k4 = (const float4*)(g_kb + (bh * NBLK + lane) * D_);
    float s = 0.f;
#pragma unroll
    for (int d4 = 0; d4 < 32; d4++) {
        float4 a = q4[d4], b = k4[d4];
        s += a.x*b.x + a.y*b.y + a.z*b.z + a.w*b.w;
    }
    float val = s;
    for (int t = 0; t < TOPK; t++) {
        float m = val; int mi = lane;
#pragma unroll
        for (int o = 16; o > 0; o >>= 1) {
            float ov = __shfl_xor_sync(0xffffffffu, m,  o);
            int   oi = __shfl_xor_sync(0xffffffffu, mi, o);
            if (ov > m || (ov == m && oi < mi)) { m = ov; mi = oi; }
        }
        if (lane == 0)  g_lut[id * TOPK + t] = mi;
        if (lane == mi) val = -3.0e38f;
    }
}

// ---------------- kernel 3: sparse block attention (3xTF32 mma) ----------------
__global__ void __launch_bounds__(256, 1)
k_sparse(const float* __restrict__ q, const float* __restrict__ k,
         const float* __restrict__ v, float* __restrict__ out)
{
    extern __shared__ float sm[];
    float* Qs = sm;                       // 64*132
    float* KV = Qs + 64 * QSTR;           // 128*136
    float* S  = KV + 128 * VSTR;          // 64*260

    int id = blockIdx.x;
    int bh = id >> 5, qb = id & 31;
    int tid  = threadIdx.x;
    int warp = tid >> 5, lane = tid & 31;
    int g = lane >> 2, t = lane & 3;
    int wm = warp >> 2, wn = warp & 3;
    const size_t bh_off = (size_t)bh * L_ * D_;
    const float scale = 0.088388347648318447f;   // 1/sqrt(128)

    // load Q tile (scaled)
    for (int i = tid; i < 64 * 32; i += 256) {
        int row = i >> 5, c4 = i & 31;
        float4 val = ((const float4*)(q + bh_off + (size_t)(qb * 64 + row) * D_))[c4];
        val.x *= scale; val.y *= scale; val.z *= scale; val.w *= scale;
        *(float4*)&Qs[row * QSTR + c4 * 4] = val;
    }

    int blks[4];
#pragma unroll
    for (int tt = 0; tt < 4; tt++) blks[tt] = g_lut[id * TOPK + tt];

    // ---- S = (Q*scale) @ K^T in two passes of 128 gathered K rows ----
    for (int pass = 0; pass < 2; pass++) {
        __syncthreads();
        for (int i = tid; i < 128 * 32; i += 256) {
            int row = i >> 5, c4 = i & 31;
            int blk = blks[pass * 2 + (row >> 6)];
            int gr  = blk * 64 + (row & 63);
            *(float4*)&KV[row * QSTR + c4 * 4] =
                ((const float4*)(k + bh_off + (size_t)gr * D_))[c4];
        }
        __syncthreads();

        float acc[2][4][4];
#pragma unroll
        for (int mt = 0; mt < 2; mt++)
#pragma unroll
            for (int nt = 0; nt < 4; nt++)
#pragma unroll
                for (int c = 0; c < 4; c++) acc[mt][nt][c] = 0.f;

        int r0 = wm * 32 + g;
        int n0 = wn * 32 + g;
#pragma unroll
        for (int ks = 0; ks < 16; ks++) {
            int kb = ks * 8;
            uint32_t ah[2][4], al[2][4], bh2[4][2], bl2[4][2];
#pragma unroll
            for (int mt = 0; mt < 2; mt++) {
                int r = r0 + mt * 16;
                split_tf32(Qs[r * QSTR + kb + t],           ah[mt][0], al[mt][0]);
                split_tf32(Qs[(r + 8) * QSTR + kb + t],     ah[mt][1], al[mt][1]);
                split_tf32(Qs[r * QSTR + kb + t + 4],       ah[mt][2], al[mt][2]);
                split_tf32(Qs[(r + 8) * QSTR + kb + t + 4], ah[mt][3], al[mt][3]);
            }
#pragma unroll
            for (int nt = 0; nt < 4; nt++) {
                int n = n0 + nt * 8;
                split_tf32(KV[n * QSTR + kb + t],     bh2[nt][0], bl2[nt][0]);
                split_tf32(KV[n * QSTR + kb + t + 4], bh2[nt][1], bl2[nt][1]);
            }
#pragma unroll
            for (int mt = 0; mt < 2; mt++)
#pragma unroll
                for (int nt = 0; nt < 4; nt++)
                    mma3(acc[mt][nt], ah[mt], al[mt], bh2[nt], bl2[nt]);
        }
#pragma unroll
        for (int mt = 0; mt < 2; mt++)
#pragma unroll
            for (int nt = 0; nt < 4; nt++) {
                int r  = wm * 32 + mt * 16 + g;
                int cc = pass * 128 + wn * 32 + nt * 8 + 2 * t;
                *(float2*)&S[r * SSTR + cc]       = make_float2(acc[mt][nt][0], acc[mt][nt][1]);
                *(float2*)&S[(r + 8) * SSTR + cc] = make_float2(acc[mt][nt][2], acc[mt][nt][3]);
            }
    }
    __syncthreads();

    // ---- row softmax over 256 ----
    for (int i = warp * 8; i < warp * 8 + 8; i++) {
        float vals[8]; float mx = -3.0e38f;
#pragma unroll
        for (int c = 0; c < 8; c++) { vals[c] = S[i * SSTR + lane + c * 32]; mx = fmaxf(mx, vals[c]); }
#pragma unroll
        for (int o = 16; o > 0; o >>= 1) mx = fmaxf(mx, __shfl_xor_sync(0xffffffffu, mx, o));
        float sum = 0.f;
#pragma unroll
        for (int c = 0; c < 8; c++) { vals[c] = __expf(vals[c] - mx); sum += vals[c]; }
#pragma unroll
        for (int o = 16; o > 0; o >>= 1) sum += __shfl_xor_sync(0xffffffffu, sum, o);
        float inv = 1.f / sum;
#pragma unroll
        for (int c = 0; c < 8; c++) S[i * SSTR + lane + c * 32] = vals[c] * inv;
    }

    // ---- O = P @ V over two V passes ----
    float o[2][4][4];
#pragma unroll
    for (int mt = 0; mt < 2; mt++)
#pragma unroll
        for (int nt = 0; nt < 4; nt++)
#pragma unroll
            for (int c = 0; c < 4; c++) o[mt][nt][c] = 0.f;

    for (int pass = 0; pass < 2; pass++) {
        __syncthreads();
        for (int i = tid; i < 128 * 32; i += 256) {
            int row = i >> 5, c4 = i & 31;
            int blk = blks[pass * 2 + (row >> 6)];
            int gr  = blk * 64 + (row & 63);
            *(float4*)&KV[row * VSTR + c4 * 4] =
                ((const float4*)(v + bh_off + (size_t)gr * D_))[c4];
        }
        __syncthreads();
#pragma unroll
        for (int ks = 0; ks < 16; ks++) {
            int kb = pass * 128 + ks * 8;   // column in S
            int jb = ks * 8;                // local V row
            uint32_t ah[2][4], al[2][4], bh2[4][2], bl2[4][2];
#pragma unroll
            for (int mt = 0; mt < 2; mt++) {
                int r = wm * 32 + mt * 16 + g;
                split_tf32(S[r * SSTR + kb + t],           ah[mt][0], al[mt][0]);
                split_tf32(S[(r + 8) * SSTR + kb + t],     ah[mt][1], al[mt][1]);
                split_tf32(S[r * SSTR + kb + t + 4],       ah[mt][2], al[mt][2]);
                split_tf32(S[(r + 8) * SSTR + kb + t + 4], ah[mt][3], al[mt][3]);
            }
#pragma unroll
            for (int nt = 0; nt < 4; nt++) {
                int d = wn * 32 + nt * 8 + g;
                split_tf32(KV[(jb + t) * VSTR + d],     bh2[nt][0], bl2[nt][0]);
                split_tf32(KV[(jb + t + 4) * VSTR + d], bh2[nt][1], bl2[nt][1]);
            }
#pragma unroll
            for (int mt = 0; mt < 2; mt++)
#pragma unroll
                for (int nt = 0; nt < 4; nt++)
                    mma3(o[mt][nt], ah[mt], al[mt], bh2[nt], bl2[nt]);
        }
    }
    float* op = out + bh_off + (size_t)(qb * 64) * D_;
#pragma unroll
    for (int mt = 0; mt < 2; mt++)
#pragma unroll
        for (int nt = 0; nt < 4; nt++) {
            int r  = wm * 32 + mt * 16 + g;
            int cc = wn * 32 + nt * 8 + 2 * t;
            *(float2*)&op[r * D_ + cc]       = make_float2(o[mt][nt][0], o[mt][nt][1]);
            *(float2*)&op[(r + 8) * D_ + cc] = make_float2(o[mt][nt][2], o[mt][nt][3]);
        }
}

// ---------------- kernel 4: kvsum/ksum via 3xTF32 mma ----------------
__global__ void __launch_bounds__(256, 1)
k_kv(const float* __restrict__ k, const float* __restrict__ v)
{
    extern __shared__ float sm[];
    float* ph = sm;                 // 128*136
    float* vv = ph + 128 * PSTR;    // 128*136

    int bh   = blockIdx.x >> 3;
    int half = blockIdx.x & 7;
    int tid  = threadIdx.x;
    int warp = tid >> 5, lane = tid & 31;
    int g = lane >> 2, t = lane & 3;
    int wm = warp >> 1, wn = warp & 1;      // warp tile: m32 (d) x n64 (e)
    const size_t bh_off = (size_t)bh * L_ * D_;

    float acc[2][8][4];
#pragma unroll
    for (int mt = 0; mt < 2; mt++)
#pragma unroll
        for (int nt = 0; nt < 8; nt++)
#pragma unroll
            for (int c = 0; c < 4; c++) acc[mt][nt][c] = 0.f;

    for (int ch = 0; ch < 2; ch++) {
        int l0 = (half * 2 + ch) * 128;
        __syncthreads();
        for (int rr = 0; rr < 16; rr++) {
            int row = warp * 16 + rr;
            size_t l = bh_off + (size_t)(l0 + row) * D_;
            float4 a = ((const float4*)(k + l))[lane];
            float m = fmaxf(fmaxf(a.x, a.y), fmaxf(a.z, a.w));
#pragma unroll
            for (int o2 = 16; o2 > 0; o2 >>= 1) m = fmaxf(m, __shfl_xor_sync(0xffffffffu, m, o2));
            float ex = __expf(a.x - m), ey = __expf(a.y - m);
            float ez = __expf(a.z - m), ew = __expf(a.w - m);
            float s = ex + ey + ez + ew;
#pragma unroll
            for (int o2 = 16; o2 > 0; o2 >>= 1) s += __shfl_xor_sync(0xffffffffu, s, o2);
            float inv = 1.f / s;
            *(float4*)&ph[row * PSTR + lane * 4] = make_float4(ex*inv, ey*inv, ez*inv, ew*inv);
            *(float4*)&vv[row * PSTR + lane * 4] = ((const float4*)(v + l))[lane];
        }
        __syncthreads();
        if (tid < 128) {
            float s = 0.f;
            for (int l = 0; l < 128; l++) s += ph[l * PSTR + tid];
            atomicAdd(&g_ksum[bh * D_ + tid], s);
        }
#pragma unroll
        for (int ks = 0; ks < 16; ks++) {
            int kb = ks * 8;
            uint32_t ah[2][4], al[2][4], bh2[8][2], bl2[8][2];
#pragma unroll
            for (int mt = 0; mt < 2; mt++) {
                int r = wm * 32 + mt * 16 + g;
                split_tf32(ph[(kb + t) * PSTR + r],         ah[mt][0], al[mt][0]);
                split_tf32(ph[(kb + t) * PSTR + r + 8],     ah[mt][1], al[mt][1]);
                split_tf32(ph[(kb + t + 4) * PSTR + r],     ah[mt][2], al[mt][2]);
                split_tf32(ph[(kb + t + 4) * PSTR + r + 8], ah[mt][3], al[mt][3]);
            }
#pragma unroll
            for (int nt = 0; nt < 8; nt++) {
                int n = wn * 64 + nt * 8 + g;
                split_tf32(vv[(kb + t) * PSTR + n],     bh2[nt][0], bl2[nt][0]);
                split_tf32(vv[(kb + t + 4) * PSTR + n], bh2[nt][1], bl2[nt][1]);
            }
#pragma unroll
            for (int mt = 0; mt < 2; mt++)
#pragma unroll
                for (int nt = 0; nt < 8; nt++)
                    mma3(acc[mt][nt], ah[mt], al[mt], bh2[nt], bl2[nt]);
        }
    }
    float* kvp = g_kvsum + bh * D_ * D_;
#pragma unroll
    for (int mt = 0; mt < 2; mt++)
#pragma unroll
        for (int nt = 0; nt < 8; nt++) {
            int d0 = wm * 32 + mt * 16 + g;
            int e0 = wn * 64 + nt * 8 + 2 * t;
            atomicAdd(&kvp[d0 * D_ + e0],           acc[mt][nt][0]);
            atomicAdd(&kvp[d0 * D_ + e0 + 1],       acc[mt][nt][1]);
            atomicAdd(&kvp[(d0 + 8) * D_ + e0],     acc[mt][nt][2]);
            atomicAdd(&kvp[(d0 + 8) * D_ + e0 + 1], acc[mt][nt][3]);
        }
}

// ---------------- kernel 5: M = kvsum @ w_proj^T (fp32, tiny) ----------------
__global__ void __launch_bounds__(256)
k_M(const float* __restrict__ w)
{
    extern __shared__ float sm[];
    float* kvt = sm;
    float* wt  = sm + 128 * QSTR;
    int bh = blockIdx.x;
    int tid = threadIdx.x;
    const float* kv = g_kvsum + bh * D_ * D_;
    for (int idx = tid; idx < D_ * D_; idx += 256) {
        int d = idx >> 7, e = idx & 127;
        kvt[e * QSTR + d] = kv[idx];
        wt [e * QSTR + d] = w[idx];
    }
    __syncthreads();
    int dg = tid >> 4, eg = tid & 15;
    float acc[8][8];
#pragma unroll
    for (int a = 0; a < 8; a++)
#pragma unroll
        for (int b2 = 0; b2 < 8; b2++) acc[a][b2] = 0.f;
    for (int e = 0; e < 128; e++) {
        float4 aA = *(const float4*)&kvt[e * QSTR + dg * 8];
        float4 aB = *(const float4*)&kvt[e * QSTR + dg * 8 + 4];
        float4 bA = *(const float4*)&wt [e * QSTR + eg * 8];
        float4 bB = *(const float4*)&wt [e * QSTR + eg * 8 + 4];
        float ad[8] = {aA.x,aA.y,aA.z,aA.w,aB.x,aB.y,aB.z,aB.w};
        float bd[8] = {bA.x,bA.y,bA.z,bA.w,bB.x,bB.y,bB.z,bB.w};
#pragma unroll
        for (int a = 0; a < 8; a++)
#pragma unroll
            for (int b2 = 0; b2 < 8; b2++) acc[a][b2] += ad[a] * bd[b2];
    }
    float* Mp = g_M + bh * D_ * D_;
#pragma unroll
    for (int a = 0; a < 8; a++)
#pragma unroll
        for (int b2 = 0; b2 < 8; b2++)
            Mp[(dg * 8 + a) * D_ + eg * 8 + b2] = acc[a][b2];
}

// ---------------- kernel 6: out += (phi_q @ M)/den + b (3xTF32 mma) ----------------
__global__ void __launch_bounds__(256, 1)
k_lin_out(const float* __restrict__ q, const float* __restrict__ bias,
          float* __restrict__ out)
{
    extern __shared__ float sm[];
    float* Ms    = sm;                 // 128*136
    float* phis  = Ms + 128 * VSTR;    // 64*132
    float* ksums = phis + 64 * QSTR;   // 128
    float* dens  = ksums + D_;         // 64
    float* bs    = dens + 64;          // 128

    int bh = blockIdx.x >> 5, cb = blockIdx.x & 31;
    int tid = threadIdx.x, warp = tid >> 5, lane = tid & 31;
    int g = lane >> 2, t = lane & 3;
    int wm = warp >> 2, wn = warp & 3;

    for (int idx = tid; idx < D_ * D_; idx += 256) {
        int row = idx >> 7, col = idx & 127;
        Ms[row * VSTR + col] = g_M[bh * D_ * D_ + idx];
    }
    if (tid < D_) { ksums[tid] = g_ksum[bh * D_ + tid]; bs[tid] = bias[tid]; }
    __syncthreads();

    const size_t base = (size_t)bh * L_ * D_ + (size_t)cb * 64 * D_;
    for (int rr = 0; rr < 8; rr++) {
        int row = warp * 8 + rr;
        float4 a = ((const float4*)(q + base + (size_t)row * D_))[lane];
        float m = fmaxf(fmaxf(a.x, a.y), fmaxf(a.z, a.w));
#pragma unroll
        for (int o = 16; o > 0; o >>= 1) m = fmaxf(m, __shfl_xor_sync(0xffffffffu, m, o));
        float ex = __expf(a.x - m), ey = __expf(a.y - m);
        float ez = __expf(a.z - m), ew = __expf(a.w - m);
        float s = ex + ey + ez + ew;
#pragma unroll
        for (int o = 16; o > 0; o >>= 1) s += __shfl_xor_sync(0xffffffffu, s, o);
        float inv = 1.f / s;
        float4 p = make_float4(ex*inv, ey*inv, ez*inv, ew*inv);
        *(float4*)&phis[row * QSTR + lane * 4] = p;
        float4 ksv = ((const float4*)ksums)[lane];
        float dp = p.x*ksv.x + p.y*ksv.y + p.z*ksv.z + p.w*ksv.w;
#pragma unroll
        for (int o = 16; o > 0; o >>= 1) dp += __shfl_xor_sync(0xffffffffu, dp, o);
        if (lane == 0) dens[row] = 1e-5f + dp;
    }
    __syncthreads();

    float acc[2][4][4];
#pragma unroll
    for (int mt = 0; mt < 2; mt++)
#pragma unroll
        for (int nt = 0; nt < 4; nt++)
#pragma unroll
            for (int c = 0; c < 4; c++) acc[mt][nt][c] = 0.f;

#pragma unroll
    for (int ks = 0; ks < 16; ks++) {
        int kb = ks * 8;
        uint32_t ah[2][4], al[2][4], bh2[4][2], bl2[4][2];
#pragma unroll
        for (int mt = 0; mt < 2; mt++) {
            int r = wm * 32 + mt * 16 + g;
            split_tf32(phis[r * QSTR + kb + t],           ah[mt][0], al[mt][0]);
            split_tf32(phis[(r + 8) * QSTR + kb + t],     ah[mt][1], al[mt][1]);
            split_tf32(phis[r * QSTR + kb + t + 4],       ah[mt][2], al[mt][2]);
            split_tf32(phis[(r + 8) * QSTR + kb + t + 4], ah[mt][3], al[mt][3]);
        }
#pragma unroll
        for (int nt = 0; nt < 4; nt++) {
            int n = wn * 32 + nt * 8 + g;
            split_tf32(Ms[(kb + t) * VSTR + n],     bh2[nt][0], bl2[nt][0]);
            split_tf32(Ms[(kb + t + 4) * VSTR + n], bh2[nt][1], bl2[nt][1]);
        }
#pragma unroll
        for (int mt = 0; mt < 2; mt++)
#pragma unroll
            for (int nt = 0; nt < 4; nt++)
                mma3(acc[mt][nt], ah[mt], al[mt], bh2[nt], bl2[nt]);
    }

    float* op = out + base;
#pragma unroll
    for (int mt = 0; mt < 2; mt++)
#pragma unroll
        for (int nt = 0; nt < 4; nt++) {
            int r  = wm * 32 + mt * 16 + g;
            int cc = wn * 32 + nt * 8 + 2 * t;
            float inv0 = 1.f / dens[r];
            float inv1 = 1.f / dens[r + 8];
            float b0 = bs[cc], b1 = bs[cc + 1];
            float2 pr0 = *(float2*)&op[r * D_ + cc];
            pr0.x += acc[mt][nt][0] * inv0 + b0;
            pr0.y += acc[mt][nt][1] * inv0 + b1;
            *(float2*)&op[r * D_ + cc] = pr0;
            float2 pr1 = *(float2*)&op[(r + 8) * D_ + cc];
            pr1.x += acc[mt][nt][2] * inv1 + b0;
            pr1.y += acc[mt][nt][3] * inv1 + b1;
            *(float2*)&op[(r + 8) * D_ + cc] = pr1;
        }
}

// ---------------- launch ----------------
extern "C" void kernel_launch(void* const* d_in, const int* in_sizes, int n_in,
                              void* d_out, int out_size)
{
    const float* q  = (const float*)d_in[0];
    const float* k  = (const float*)d_in[1];
    const float* v  = (const float*)d_in[2];
    const float* w  = (const float*)d_in[3];
    const float* bp = (const float*)d_in[4];
    float* out = (float*)d_out;

    const int sp_smem = (64*QSTR + 128*VSTR + 64*SSTR) * (int)sizeof(float);
    const int kv_smem = (2 * 128 * PSTR) * (int)sizeof(float);
    const int m_smem  = (2 * 128 * QSTR) * (int)sizeof(float);
    const int lo_smem = (128*VSTR + 64*QSTR + D_ + 64 + D_) * (int)sizeof(float);

    cudaFuncSetAttribute(k_sparse,  cudaFuncAttributeMaxDynamicSharedMemorySize, sp_smem);
    cudaFuncSetAttribute(k_kv,      cudaFuncAttributeMaxDynamicSharedMemorySize, kv_smem);
    cudaFuncSetAttribute(k_M,       cudaFuncAttributeMaxDynamicSharedMemorySize, m_smem);
    cudaFuncSetAttribute(k_lin_out, cudaFuncAttributeMaxDynamicSharedMemorySize, lo_smem);

    void* kvp = nullptr; void* ksp = nullptr;
    cudaGetSymbolAddress(&kvp, g_kvsum);
    cudaGetSymbolAddress(&ksp, g_ksum);
    cudaMemsetAsync(kvp, 0, sizeof(float) * BH * D_ * D_);
    cudaMemsetAsync(ksp, 0, sizeof(float) * BH * D_);

    k_blockmean<<<2048, 128>>>(q, k);
    k_topk<<<1024, 32>>>();
    k_sparse<<<1024, 256, sp_smem>>>(q, k, v, out);
    k_kv<<<256, 256, kv_smem>>>(k, v);
    k_M<<<32, 256, m_smem>>>(w);
    k_lin_out<<<1024, 256, lo_smem>>>(q, bp, out);
}